// round 9
// baseline (speedup 1.0000x reference)
#include <cuda_runtime.h>
#include <math.h>

// ---------------- problem constants ----------------
#define TSTEPS 1000
#define NIN    4096
#define RN     4000
#define OUTW   (2*RN)
#define ALPHA  0.5f

// ---------------- persistent loop config ----------------
#define NBLK   125             // 125 tiles x 32 columns = 4000
#define NTHR   1024

#define NNZ_CAP 1800000

// ---------------- device scratch ----------------
__device__ float          d_vals1[NNZ_CAP];
__device__ unsigned short d_rows1[NNZ_CAP];
__device__ float          d_vals2[NNZ_CAP];
__device__ unsigned short d_rows2[NNZ_CAP];
__device__ int            d_colptr1[RN+1];
__device__ int            d_colptr2[RN+1];
__device__ int            d_cntW1[8*RN];
__device__ int            d_cntW2[8*RN];
__device__ float          d_U1[TSTEPS*RN];    // x @ Win1   (16 MB)
__device__ float          d_U2[TSTEPS*RN];    // V1 @ Win2  (16 MB)
__device__ float          d_v[2][RN];         // hot ping-pong state
__device__ volatile unsigned d_stamp1[NBLK];  // per-tile progress stamps
__device__ volatile unsigned d_stamp2[NBLK];

// ---------------- packed f32x2 helpers (sm_103a FFMA2 pipe) -----------------
__device__ __forceinline__ unsigned long long dupf2(float v) {
    unsigned long long r;
    asm("mov.b64 %0, {%1, %2};" : "=l"(r) : "f"(v), "f"(v));
    return r;
}
__device__ __forceinline__ void fmaf2(unsigned long long &d,
                                      unsigned long long a,
                                      unsigned long long b) {
    asm("fma.rn.f32x2 %0, %1, %2, %0;" : "+l"(d) : "l"(a), "l"(b));
}
__device__ __forceinline__ float2 unpk(unsigned long long v) {
    float2 r;
    asm("mov.b64 {%0, %1}, %2;" : "=f"(r.x), "=f"(r.y) : "l"(v));
    return r;
}

// ---------------- scoped sync primitives ----------------
__device__ __forceinline__ unsigned ldAcq(volatile unsigned* p) {
    unsigned v;
    asm volatile("ld.acquire.gpu.global.u32 %0, [%1];"
                 : "=r"(v) : "l"((const unsigned*)p) : "memory");
    return v;
}
__device__ __forceinline__ void stRel(volatile unsigned* p, unsigned v) {
    asm volatile("st.release.gpu.global.u32 [%0], %1;"
                 :: "l"((unsigned*)p), "r"(v) : "memory");
}

// ---------------- init (reset stamps every replay — graph determinism) ------
__global__ void initKernel() {
    int idx = threadIdx.x;
    if (idx < NBLK) { d_stamp1[idx] = 0u; d_stamp2[idx] = 0u; }
}

// ---------------- sparse build: per-warp-range counts ----------------
__global__ void countKernel(const float* __restrict__ W1,
                            const float* __restrict__ W2) {
    int b = blockIdx.x;
    const float* W; int* cntW; int j0;
    if (b < 125) { W = W1; cntW = d_cntW1; j0 = b * 32; }
    else         { W = W2; cntW = d_cntW2; j0 = (b - 125) * 32; }
    int w = threadIdx.x >> 5, lane = threadIdx.x & 31;
    int j = j0 + lane;
    int c = 0;
    int i0 = w * 500, i1 = i0 + 500;
    for (int i = i0; i < i1; i++) c += (W[(size_t)i * RN + j] != 0.f);
    cntW[w * RN + j] = c;
}

// ---------------- exclusive scan ----------------
__global__ void scanKernel() {
    __shared__ int sA[4096], sB[4096];
    const int* cntW = (blockIdx.x == 0) ? d_cntW1 : d_cntW2;
    int* colptr     = (blockIdx.x == 0) ? d_colptr1 : d_colptr2;
    int tid = threadIdx.x;
    for (int i = tid; i < 4096; i += blockDim.x) {
        int tot = 0;
        if (i < RN)
            for (int w = 0; w < 8; w++) tot += cntW[w * RN + i];
        sA[i] = tot;
    }
    __syncthreads();
    int* src = sA; int* dst = sB;
    for (int off = 1; off < 4096; off <<= 1) {
        for (int i = tid; i < 4096; i += blockDim.x)
            dst[i] = src[i] + (i >= off ? src[i - off] : 0);
        __syncthreads();
        int* t = src; src = dst; dst = t;
    }
    for (int i = tid; i < RN; i += blockDim.x) colptr[i + 1] = src[i];
    if (tid == 0) colptr[0] = 0;
}

// ---------------- fill CSC ----------------
__global__ void fillKernel(const float* __restrict__ W1,
                           const float* __restrict__ W2) {
    int b = blockIdx.x;
    const float* W; const int* cntW; const int* colptr;
    float* vals; unsigned short* rows; int j0;
    if (b < 125) { W = W1; cntW = d_cntW1; colptr = d_colptr1;
                   vals = d_vals1; rows = d_rows1; j0 = b * 32; }
    else         { W = W2; cntW = d_cntW2; colptr = d_colptr2;
                   vals = d_vals2; rows = d_rows2; j0 = (b - 125) * 32; }
    int w = threadIdx.x >> 5, lane = threadIdx.x & 31;
    int j = j0 + lane;
    int p = colptr[j];
    for (int w2 = 0; w2 < 8; w2++)
        if (w2 < w) p += cntW[w2 * RN + j];
    int i0 = w * 500, i1 = i0 + 500;
    for (int i = i0; i < i1; i++) {
        float v = W[(size_t)i * RN + j];
        if (v != 0.f) { vals[p] = v; rows[p] = (unsigned short)i; p++; }
    }
}

// ---------------- SGEMM (f32x2 packed, reg double-buffer) -------------------
// C = which ? d_U2 : d_U1 (resolved in device code; device globals must never
// be passed as host-side kernel args — that was the R3/R4 bug).
__global__ __launch_bounds__(256) void sgemmK(const float* __restrict__ A,
                                              const float* __restrict__ B,
                                              int which,
                                              int M, int N, int K,
                                              int lda, int ldb, int ldc) {
    float* __restrict__ C = which ? d_U2 : d_U1;
    __shared__ float As[8][128];
    __shared__ float Bs[8][128];
    int tid = threadIdx.x;
    int tx = tid % 16, ty = tid / 16;
    int row0 = blockIdx.y * 128, col0 = blockIdx.x * 128;

    unsigned long long acc2[4][8];   // [row-pair][col]
#pragma unroll
    for (int p = 0; p < 4; p++)
#pragma unroll
        for (int j = 0; j < 8; j++) acc2[p][j] = 0ull;

    const int aRow = tid >> 1;
    const int aCol = (tid & 1) * 4;
    const int bRow = tid >> 5;
    const int bCol = (tid & 31) * 4;

    float4 a4 = make_float4(0.f, 0.f, 0.f, 0.f);
    if (row0 + aRow < M)
        a4 = *(const float4*)(A + (size_t)(row0 + aRow) * lda + aCol);
    float4 b4 = make_float4(0.f, 0.f, 0.f, 0.f);
    if (col0 + bCol < N)
        b4 = *(const float4*)(B + (size_t)bRow * ldb + col0 + bCol);

    for (int k0 = 0; k0 < K; k0 += 8) {
        As[aCol + 0][aRow] = a4.x; As[aCol + 1][aRow] = a4.y;
        As[aCol + 2][aRow] = a4.z; As[aCol + 3][aRow] = a4.w;
        *(float4*)(&Bs[bRow][bCol]) = b4;
        __syncthreads();

        if (k0 + 8 < K) {
            if (row0 + aRow < M)
                a4 = *(const float4*)(A + (size_t)(row0 + aRow) * lda + k0 + 8 + aCol);
            if (col0 + bCol < N)
                b4 = *(const float4*)(B + (size_t)(k0 + 8 + bRow) * ldb + col0 + bCol);
        }

#pragma unroll
        for (int kk = 0; kk < 8; kk++) {
            float4 a0 = *(const float4*)(&As[kk][ty * 4]);
            float4 a1 = *(const float4*)(&As[kk][64 + ty * 4]);
            float4 bb0 = *(const float4*)(&Bs[kk][tx * 4]);
            float4 bb1 = *(const float4*)(&Bs[kk][64 + tx * 4]);
            unsigned long long ap[4];
            ap[0] = reinterpret_cast<const ulonglong2*>(&a0)->x;
            ap[1] = reinterpret_cast<const ulonglong2*>(&a0)->y;
            ap[2] = reinterpret_cast<const ulonglong2*>(&a1)->x;
            ap[3] = reinterpret_cast<const ulonglong2*>(&a1)->y;
            unsigned long long bd[8];
            bd[0] = dupf2(bb0.x); bd[1] = dupf2(bb0.y);
            bd[2] = dupf2(bb0.z); bd[3] = dupf2(bb0.w);
            bd[4] = dupf2(bb1.x); bd[5] = dupf2(bb1.y);
            bd[6] = dupf2(bb1.z); bd[7] = dupf2(bb1.w);
#pragma unroll
            for (int p = 0; p < 4; p++)
#pragma unroll
                for (int j = 0; j < 8; j++)
                    fmaf2(acc2[p][j], ap[p], bd[j]);
        }
        __syncthreads();
    }

#pragma unroll
    for (int p = 0; p < 4; p++) {
        float2 u[8];
#pragma unroll
        for (int j = 0; j < 8; j++) u[j] = unpk(acc2[p][j]);
#pragma unroll
        for (int h = 0; h < 2; h++) {
            int i = 2 * p + h;
            int r = row0 + ((i < 4) ? (ty * 4 + i) : (64 + ty * 4 + i - 4));
            if (r >= M) continue;
            float4 v0 = make_float4(h ? u[0].y : u[0].x, h ? u[1].y : u[1].x,
                                    h ? u[2].y : u[2].x, h ? u[3].y : u[3].x);
            float4 v1 = make_float4(h ? u[4].y : u[4].x, h ? u[5].y : u[5].x,
                                    h ? u[6].y : u[6].x, h ? u[7].y : u[7].x);
            int c0 = col0 + tx * 4;
            int c1 = col0 + 64 + tx * 4;
            if (c0 < N) *(float4*)(C + (size_t)r * ldc + c0) = v0;
            if (c1 < N) *(float4*)(C + (size_t)r * ldc + c1) = v1;
        }
    }
}

// ---------------- sparse recurrence with DATA-FLOW sync ---------------------
// No global barrier. Block b owns columns [b*32, b*32+32) = "tile b".
// Publish protocol: write 32 floats to d_v[t&1] (+ archive), __syncwarp,
//                   st.release stamp[b] = t+1.
// Consume protocol: per warp, for each owned tile s: spin ld.acquire
//                   stamp[s] >= t, then load that 128B tile into smem.
// Depth-2 ping-pong is safe: computing t+1 requires all stamps >= t+0? no —
// staging v(t) saw stamps >= t+1? (stamp value = steps completed). A stamp of
// t means that block fully READ step t-1 before publishing, so overwriting
// the (t-1)-parity buffer after seeing all stamps >= t is race-free.
__device__ __forceinline__ void esn_chain(const int* __restrict__ colptr,
                                          const float* __restrict__ gvals,
                                          const unsigned short* __restrict__ grows,
                                          const float* __restrict__ U,
                                          float* __restrict__ out, int ofs,
                                          volatile unsigned* stamp) {
    __shared__ float vs[RN];
    __shared__ float ovals[32];
    __shared__ int s_cst[33];

    const int tid  = threadIdx.x;
    const int lane = tid & 31;
    const int wrp  = tid >> 5;          // 0..31 -> one column each
    const int b    = blockIdx.x;
    const int j0   = b * 32;

    if (tid < 33) s_cst[tid] = __ldg(&colptr[j0 + tid]);

    // t = 0 : v(0) = 0.5*tanh(U[0]); publish stamp = 1
    if (tid < 32) {
        int j = j0 + tid;
        float vn = ALPHA * tanhf(__ldg(&U[j]));
        ovals[tid] = vn;
        __stcg(&d_v[0][j], vn);
        __stcs(&out[(size_t)0 * OUTW + ofs + j], vn);
        __syncwarp();
        if (tid == 0) stRel(&stamp[b], 1u);
    }
    __syncthreads();                    // ovals + s_cst visible block-wide

    for (int t = 1; t < TSTEPS; t++) {
        const float* __restrict__ vsrc = d_v[(t - 1) & 1];
        float*       __restrict__ vdst = d_v[t & 1];

        // prefetch U[t] (independent of staging)
        float uval = 0.f;
        if (lane == 0) uval = __ldg(&U[(size_t)t * RN + j0 + wrp]);

        // ---- stage v(t-1): per-tile poll + 128B load, pipelined per warp ----
        for (int s = wrp; s < NBLK; s += 32) {
            if (s == b) {
                vs[j0 + lane] = ovals[lane];      // own tile: smem copy, no RT
            } else {
                while (ldAcq(&stamp[s]) < (unsigned)t) { }   // all lanes, 1 word
                vs[s * 32 + lane] = __ldcg(&vsrc[s * 32 + lane]);
            }
        }
        __syncthreads();

        // ---- warp w -> column j0+w ----
        {
            const int ps = s_cst[wrp];
            const int pe = s_cst[wrp + 1];
            float acc = 0.f;
            for (int p = ps + lane; p < pe; p += 32)
                acc += __ldg(&gvals[p]) * vs[__ldg(&grows[p])];
#pragma unroll
            for (int off = 16; off > 0; off >>= 1)
                acc += __shfl_down_sync(0xffffffffu, acc, off);
            if (lane == 0) {
                float z = acc + uval;
                ovals[wrp] = (1.f - ALPHA) * vs[j0 + wrp] + ALPHA * tanhf(z);
            }
        }
        __syncthreads();

        // ---- publish: coalesced data stores, then release stamp ----
        if (tid < 32) {
            float vn = ovals[tid];
            __stcg(&vdst[j0 + tid], vn);
            __stcs(&out[(size_t)t * OUTW + ofs + j0 + tid], vn);
            __syncwarp();
            if (tid == 0) stRel(&stamp[b], (unsigned)(t + 1));
        }
        // no block-wide sync needed here: next staging re-waits on stamps,
        // and vs/ovals rewrites are ordered by the staging __syncthreads.
    }
}

__global__ __launch_bounds__(NTHR, 1) void esn1Kernel(float* __restrict__ out) {
    esn_chain(d_colptr1, d_vals1, d_rows1, d_U1, out, 0, d_stamp1);
}

__global__ __launch_bounds__(NTHR, 1) void esn2Kernel(float* __restrict__ out) {
    esn_chain(d_colptr2, d_vals2, d_rows2, d_U2, out, RN, d_stamp2);
}

// ---------------- launch ----------------
extern "C" void kernel_launch(void* const* d_in, const int* in_sizes, int n_in,
                              void* d_out, int out_size) {
    const float* x    = (const float*)d_in[0];
    const float* Win1 = (const float*)d_in[1];
    const float* W1   = (const float*)d_in[2];
    const float* Win2 = (const float*)d_in[3];
    const float* W2   = (const float*)d_in[4];
    float* out = (float*)d_out;
    (void)in_sizes; (void)n_in; (void)out_size;

    initKernel<<<1, 256>>>();
    countKernel<<<250, 256>>>(W1, W2);
    scanKernel<<<2, 1024>>>();
    fillKernel<<<250, 256>>>(W1, W2);

    dim3 gg((RN + 127) / 128, (TSTEPS + 127) / 128);
    // U1 = x[1000,4096] @ Win1[4096,4000]
    sgemmK<<<gg, 256>>>(x, Win1, 0, TSTEPS, RN, NIN, NIN, RN, RN);

    // v1 chain -> out[:, 0:4000]
    esn1Kernel<<<NBLK, NTHR>>>(out);

    // U2 = V1[1000,4000] @ Win2[4000,4000]  (V1 rows in out, stride OUTW)
    sgemmK<<<gg, 256>>>(out, Win2, 1, TSTEPS, RN, RN, OUTW, RN, RN);

    // v2 chain -> out[:, 4000:8000]
    esn2Kernel<<<NBLK, NTHR>>>(out);
}

// round 10
// speedup vs baseline: 2.8949x; 2.8949x over previous
#include <cuda_runtime.h>
#include <math.h>

// ---------------- problem constants ----------------
#define TSTEPS 1000
#define NIN    4096
#define RN     4000
#define OUTW   (2*RN)
#define ALPHA  0.5f

// ---------------- persistent loop config ----------------
#define NBLK   125             // 125 tiles x 32 columns = 4000
#define NTHR   1024

#define NNZ_CAP 1800000

// ---------------- device scratch ----------------
__device__ float          d_vals1[NNZ_CAP];
__device__ unsigned short d_rows1[NNZ_CAP];
__device__ float          d_vals2[NNZ_CAP];
__device__ unsigned short d_rows2[NNZ_CAP];
__device__ int            d_colptr1[RN+1];
__device__ int            d_colptr2[RN+1];
__device__ int            d_cntW1[8*RN];
__device__ int            d_cntW2[8*RN];
__device__ float          d_U1[TSTEPS*RN];    // x @ Win1   (16 MB)
__device__ float          d_U2[TSTEPS*RN];    // V1 @ Win2  (16 MB)
__device__ float          d_v[2][RN];         // hot ping-pong state
__device__ unsigned       g_ctr1;             // monotonic barrier counters
__device__ unsigned       g_ctr2;

// ---------------- packed f32x2 helpers (sm_103a FFMA2 pipe) -----------------
__device__ __forceinline__ unsigned long long dupf2(float v) {
    unsigned long long r;
    asm("mov.b64 %0, {%1, %2};" : "=l"(r) : "f"(v), "f"(v));
    return r;
}
__device__ __forceinline__ void fmaf2(unsigned long long &d,
                                      unsigned long long a,
                                      unsigned long long b) {
    asm("fma.rn.f32x2 %0, %1, %2, %0;" : "+l"(d) : "l"(a), "l"(b));
}
__device__ __forceinline__ float2 unpk(unsigned long long v) {
    float2 r;
    asm("mov.b64 {%0, %1}, %2;" : "=f"(r.x), "=f"(r.y) : "l"(v));
    return r;
}

// ---------------- scoped sync primitives ----------------
__device__ __forceinline__ void redAddRel(unsigned* p) {
    asm volatile("red.release.gpu.global.add.u32 [%0], 1;"
                 :: "l"(p) : "memory");
}
__device__ __forceinline__ unsigned ldAcq(const unsigned* p) {
    unsigned v;
    asm volatile("ld.acquire.gpu.global.u32 %0, [%1];"
                 : "=r"(v) : "l"(p) : "memory");
    return v;
}

// ---------------- init (reset counters every replay — graph determinism) ----
__global__ void initKernel() {
    if (threadIdx.x == 0) { g_ctr1 = 0u; g_ctr2 = 0u; }
}

// ---------------- sparse build: per-warp-range counts ----------------
__global__ void countKernel(const float* __restrict__ W1,
                            const float* __restrict__ W2) {
    int b = blockIdx.x;
    const float* W; int* cntW; int j0;
    if (b < 125) { W = W1; cntW = d_cntW1; j0 = b * 32; }
    else         { W = W2; cntW = d_cntW2; j0 = (b - 125) * 32; }
    int w = threadIdx.x >> 5, lane = threadIdx.x & 31;
    int j = j0 + lane;
    int c = 0;
    int i0 = w * 500, i1 = i0 + 500;
    for (int i = i0; i < i1; i++) c += (W[(size_t)i * RN + j] != 0.f);
    cntW[w * RN + j] = c;
}

// ---------------- exclusive scan ----------------
__global__ void scanKernel() {
    __shared__ int sA[4096], sB[4096];
    const int* cntW = (blockIdx.x == 0) ? d_cntW1 : d_cntW2;
    int* colptr     = (blockIdx.x == 0) ? d_colptr1 : d_colptr2;
    int tid = threadIdx.x;
    for (int i = tid; i < 4096; i += blockDim.x) {
        int tot = 0;
        if (i < RN)
            for (int w = 0; w < 8; w++) tot += cntW[w * RN + i];
        sA[i] = tot;
    }
    __syncthreads();
    int* src = sA; int* dst = sB;
    for (int off = 1; off < 4096; off <<= 1) {
        for (int i = tid; i < 4096; i += blockDim.x)
            dst[i] = src[i] + (i >= off ? src[i - off] : 0);
        __syncthreads();
        int* t = src; src = dst; dst = t;
    }
    for (int i = tid; i < RN; i += blockDim.x) colptr[i + 1] = src[i];
    if (tid == 0) colptr[0] = 0;
}

// ---------------- fill CSC ----------------
__global__ void fillKernel(const float* __restrict__ W1,
                           const float* __restrict__ W2) {
    int b = blockIdx.x;
    const float* W; const int* cntW; const int* colptr;
    float* vals; unsigned short* rows; int j0;
    if (b < 125) { W = W1; cntW = d_cntW1; colptr = d_colptr1;
                   vals = d_vals1; rows = d_rows1; j0 = b * 32; }
    else         { W = W2; cntW = d_cntW2; colptr = d_colptr2;
                   vals = d_vals2; rows = d_rows2; j0 = (b - 125) * 32; }
    int w = threadIdx.x >> 5, lane = threadIdx.x & 31;
    int j = j0 + lane;
    int p = colptr[j];
    for (int w2 = 0; w2 < 8; w2++)
        if (w2 < w) p += cntW[w2 * RN + j];
    int i0 = w * 500, i1 = i0 + 500;
    for (int i = i0; i < i1; i++) {
        float v = W[(size_t)i * RN + j];
        if (v != 0.f) { vals[p] = v; rows[p] = (unsigned short)i; p++; }
    }
}

// ---------------- SGEMM (f32x2 packed, reg double-buffer) -------------------
// C = which ? d_U2 : d_U1 (resolved in device code; device globals must never
// be passed as host-side kernel args — that was the R3/R4 bug).
__global__ __launch_bounds__(256) void sgemmK(const float* __restrict__ A,
                                              const float* __restrict__ B,
                                              int which,
                                              int M, int N, int K,
                                              int lda, int ldb, int ldc) {
    float* __restrict__ C = which ? d_U2 : d_U1;
    __shared__ float As[8][128];
    __shared__ float Bs[8][128];
    int tid = threadIdx.x;
    int tx = tid % 16, ty = tid / 16;
    int row0 = blockIdx.y * 128, col0 = blockIdx.x * 128;

    unsigned long long acc2[4][8];   // [row-pair][col]
#pragma unroll
    for (int p = 0; p < 4; p++)
#pragma unroll
        for (int j = 0; j < 8; j++) acc2[p][j] = 0ull;

    const int aRow = tid >> 1;
    const int aCol = (tid & 1) * 4;
    const int bRow = tid >> 5;
    const int bCol = (tid & 31) * 4;

    float4 a4 = make_float4(0.f, 0.f, 0.f, 0.f);
    if (row0 + aRow < M)
        a4 = *(const float4*)(A + (size_t)(row0 + aRow) * lda + aCol);
    float4 b4 = make_float4(0.f, 0.f, 0.f, 0.f);
    if (col0 + bCol < N)
        b4 = *(const float4*)(B + (size_t)bRow * ldb + col0 + bCol);

    for (int k0 = 0; k0 < K; k0 += 8) {
        As[aCol + 0][aRow] = a4.x; As[aCol + 1][aRow] = a4.y;
        As[aCol + 2][aRow] = a4.z; As[aCol + 3][aRow] = a4.w;
        *(float4*)(&Bs[bRow][bCol]) = b4;
        __syncthreads();

        if (k0 + 8 < K) {
            if (row0 + aRow < M)
                a4 = *(const float4*)(A + (size_t)(row0 + aRow) * lda + k0 + 8 + aCol);
            if (col0 + bCol < N)
                b4 = *(const float4*)(B + (size_t)(k0 + 8 + bRow) * ldb + col0 + bCol);
        }

#pragma unroll
        for (int kk = 0; kk < 8; kk++) {
            float4 a0 = *(const float4*)(&As[kk][ty * 4]);
            float4 a1 = *(const float4*)(&As[kk][64 + ty * 4]);
            float4 bb0 = *(const float4*)(&Bs[kk][tx * 4]);
            float4 bb1 = *(const float4*)(&Bs[kk][64 + tx * 4]);
            unsigned long long ap[4];
            ap[0] = reinterpret_cast<const ulonglong2*>(&a0)->x;
            ap[1] = reinterpret_cast<const ulonglong2*>(&a0)->y;
            ap[2] = reinterpret_cast<const ulonglong2*>(&a1)->x;
            ap[3] = reinterpret_cast<const ulonglong2*>(&a1)->y;
            unsigned long long bd[8];
            bd[0] = dupf2(bb0.x); bd[1] = dupf2(bb0.y);
            bd[2] = dupf2(bb0.z); bd[3] = dupf2(bb0.w);
            bd[4] = dupf2(bb1.x); bd[5] = dupf2(bb1.y);
            bd[6] = dupf2(bb1.z); bd[7] = dupf2(bb1.w);
#pragma unroll
            for (int p = 0; p < 4; p++)
#pragma unroll
                for (int j = 0; j < 8; j++)
                    fmaf2(acc2[p][j], ap[p], bd[j]);
        }
        __syncthreads();
    }

#pragma unroll
    for (int p = 0; p < 4; p++) {
        float2 u[8];
#pragma unroll
        for (int j = 0; j < 8; j++) u[j] = unpk(acc2[p][j]);
#pragma unroll
        for (int h = 0; h < 2; h++) {
            int i = 2 * p + h;
            int r = row0 + ((i < 4) ? (ty * 4 + i) : (64 + ty * 4 + i - 4));
            if (r >= M) continue;
            float4 v0 = make_float4(h ? u[0].y : u[0].x, h ? u[1].y : u[1].x,
                                    h ? u[2].y : u[2].x, h ? u[3].y : u[3].x);
            float4 v1 = make_float4(h ? u[4].y : u[4].x, h ? u[5].y : u[5].x,
                                    h ? u[6].y : u[6].x, h ? u[7].y : u[7].x);
            int c0 = col0 + tx * 4;
            int c1 = col0 + 64 + tx * 4;
            if (c0 < N) *(float4*)(C + (size_t)r * ldc + c0) = v0;
            if (c1 < N) *(float4*)(C + (size_t)r * ldc + c1) = v1;
        }
    }
}

// ---------------- grid barrier: RED arrival + counter poll ------------------
// __syncthreads establishes block-scope HB to tid0; red.release.gpu publishes;
// pollers use ld.acquire on the SAME counter (counter value itself = release).
// One poller per block (lesson from R9: never distribute the polls).
__device__ __forceinline__ void gsyncC(unsigned target, unsigned* ctr) {
    __syncthreads();
    if (threadIdx.x == 0) {
        redAddRel(ctr);                  // fire-and-forget arrival
        while (ldAcq(ctr) < target) { }  // detect: counter reaches target
    }
    __syncthreads();
}

// ---------------- sparse-only recurrence (shared by both chains) ------------
// Block b owns columns [b*32, b*32+32). CSC slice is L1-resident after step 1.
// State ping-pongs through hot d_v[2]; out rows are archive-only (read by the
// NEXT kernel launch, so only kernel-boundary visibility is required).
// v(t) = 0.5*v(t-1) + 0.5*tanh( v(t-1)@W + U[t] ),  v(-1)=0
// Depth-2 safety: a block writes d_v[(t+1)&1] only after barrier gen t+1,
// which requires every block to have finished READING d_v[(t-1)&1] (same
// parity) during its step-t staging. Race-free with 1 barrier/step.
__device__ __forceinline__ void esn_chain(const int* __restrict__ colptr,
                                          const float* __restrict__ gvals,
                                          const unsigned short* __restrict__ grows,
                                          const float* __restrict__ U,
                                          float* __restrict__ out, int ofs,
                                          unsigned* ctr) {
    __shared__ float vs[RN];
    __shared__ int s_cst[33];

    const int tid  = threadIdx.x;
    const int lane = tid & 31;
    const int wrp  = tid >> 5;          // 0..31 -> one column each
    const int j0   = blockIdx.x * 32;

    if (tid < 33) s_cst[tid] = __ldg(&colptr[j0 + tid]);

    // t = 0 : v(0) = 0.5*tanh(U[0])
    if (tid < 32) {
        int j = j0 + tid;
        float vn = ALPHA * tanhf(__ldg(&U[j]));
        d_v[0][j] = vn;
        out[(size_t)0 * OUTW + ofs + j] = vn;
    }
    gsyncC(1u * NBLK, ctr);             // also orders s_cst for the loop

    for (int t = 1; t < TSTEPS; t++) {
        const float* __restrict__ vsrc = d_v[(t - 1) & 1];
        float*       __restrict__ vdst = d_v[t & 1];

        // prefetch U[t] (independent of staging)
        float uval = 0.f;
        if (lane == 0) uval = __ldg(&U[(size_t)t * RN + j0 + wrp]);

        // stage v(t-1) into smem (bypass L1: written by other SMs)
        const float4* vp = reinterpret_cast<const float4*>(vsrc);
        for (int i = tid; i < RN / 4; i += NTHR)
            reinterpret_cast<float4*>(vs)[i] = __ldcg(vp + i);
        __syncthreads();

        // warp w -> column j0+w; publish immediately when done
        {
            const int ps = s_cst[wrp];
            const int pe = s_cst[wrp + 1];
            float acc = 0.f;
            for (int p = ps + lane; p < pe; p += 32)
                acc += __ldg(&gvals[p]) * vs[__ldg(&grows[p])];
#pragma unroll
            for (int off = 16; off > 0; off >>= 1)
                acc += __shfl_down_sync(0xffffffffu, acc, off);
            if (lane == 0) {
                const int j = j0 + wrp;
                float z  = acc + uval;
                float vn = (1.f - ALPHA) * vs[j] + ALPHA * tanhf(z);
                vdst[j] = vn;                              // hot publish
                out[(size_t)t * OUTW + ofs + j] = vn;      // archive
            }
        }

        if (t < TSTEPS - 1)
            gsyncC((unsigned)(t + 1) * NBLK, ctr);
    }
}

__global__ __launch_bounds__(NTHR, 1) void esn1Kernel(float* __restrict__ out) {
    esn_chain(d_colptr1, d_vals1, d_rows1, d_U1, out, 0, &g_ctr1);
}

__global__ __launch_bounds__(NTHR, 1) void esn2Kernel(float* __restrict__ out) {
    esn_chain(d_colptr2, d_vals2, d_rows2, d_U2, out, RN, &g_ctr2);
}

// ---------------- launch ----------------
extern "C" void kernel_launch(void* const* d_in, const int* in_sizes, int n_in,
                              void* d_out, int out_size) {
    const float* x    = (const float*)d_in[0];
    const float* Win1 = (const float*)d_in[1];
    const float* W1   = (const float*)d_in[2];
    const float* Win2 = (const float*)d_in[3];
    const float* W2   = (const float*)d_in[4];
    float* out = (float*)d_out;
    (void)in_sizes; (void)n_in; (void)out_size;

    initKernel<<<1, 32>>>();
    countKernel<<<250, 256>>>(W1, W2);
    scanKernel<<<2, 1024>>>();
    fillKernel<<<250, 256>>>(W1, W2);

    dim3 gg((RN + 127) / 128, (TSTEPS + 127) / 128);
    // U1 = x[1000,4096] @ Win1[4096,4000]
    sgemmK<<<gg, 256>>>(x, Win1, 0, TSTEPS, RN, NIN, NIN, RN, RN);

    // v1 chain -> out[:, 0:4000]
    esn1Kernel<<<NBLK, NTHR>>>(out);

    // U2 = V1[1000,4000] @ Win2[4000,4000]  (V1 rows in out, stride OUTW)
    sgemmK<<<gg, 256>>>(out, Win2, 1, TSTEPS, RN, RN, OUTW, RN, RN);

    // v2 chain -> out[:, 4000:8000]
    esn2Kernel<<<NBLK, NTHR>>>(out);
}